// round 13
// baseline (speedup 1.0000x reference)
#include <cuda_runtime.h>
#include <cuda_fp16.h>

#define BB 16
#define TT 96
#define TP1 97
#define HW 16384
#define NSTEP 6
#define MTHR 0.9f
#define NBLK 1024           // 8 blocks/SM * 148 SMs = 1184 >= 1024 (co-resident)
#define PXB 256             // pixels owned per block (both phases)
#define BPB 64              // blocks per batch (4 tiles of 64 px each)

// ---- scratch (device globals; no allocation APIs) ----
__device__ __half        g_D[(size_t)BB * HW * TT]; // d[b][p][t] fp16, t contiguous (~50MB)
__device__ double        g_delta[BB * TP1];         // idx0 = empty template, always 0
__device__ unsigned char g_topcov[BB * HW];
__device__ float         g_topval[BB * HW];
__device__ int           g_bcnt[8];                 // barrier arrival counters
__device__ int           g_bgen[8];                 // barrier generations (monotonic)

// ---------------------------------------------------------------------------
// Grid-wide sense-reversing barrier; gen is monotonic (graph-replay safe).
__device__ __forceinline__ void grid_barrier(int slot) {
    __syncthreads();
    __threadfence();
    if (threadIdx.x == 0) {
        int g   = atomicAdd(&g_bgen[slot], 0);
        int old = atomicAdd(&g_bcnt[slot], 1);
        if (old == NBLK - 1) {
            g_bcnt[slot] = 0;
            __threadfence();
            atomicExch(&g_bgen[slot], g + 1);
        } else {
            while (atomicAdd(&g_bgen[slot], 0) == g) __nanosleep(64);
        }
    }
    __syncthreads();
    __threadfence();
}

// ---------------------------------------------------------------------------
struct SmemPre { float xs[64]; float eb[64]; float dsm[64][TP1]; };
struct SmemStep { int list[PXB]; unsigned wm[4]; int scid; };
union SmemU { SmemPre pre; SmemStep st; };

__global__ void __launch_bounds__(128, 8)
k_all(const float* __restrict__ x,
      const float* __restrict__ temps,
      const float* __restrict__ msks,
      const float* __restrict__ bg,
      float* __restrict__ out) {
    __shared__ SmemU sm;
    __shared__ float accd[TT];           // phase-A delta0 accumulator (rounded values)
    __shared__ unsigned char used[TP1];

    const int tid = threadIdx.x;
    const int blk = blockIdx.x;
    const int b   = blk >> 6;            // 64 blocks per batch
    const int jj  = blk & 63;
    const int p0g = jj * PXB;            // block's 256-pixel slice

    if (tid < TP1) used[tid] = 0;
    if (tid < TT)  accd[tid] = 0.f;

    // --- zero g_delta, visible before any publish ---
    if (blk < BB && tid < TP1) g_delta[blk * TP1 + tid] = 0.0;
    grid_barrier(7);

    // ============ Phase A: precompute D (fp16) + delta0 on own 4 tiles ======
    for (int ti = 0; ti < 4; ti++) {
        const int p0 = p0g + ti * 64;

        if (tid < 64) {
            float xv = x[b * HW + p0 + tid];
            float bv = bg[p0 + tid];
            sm.pre.xs[tid] = xv;
            float e = xv - bv;
            sm.pre.eb[tid] = e * e;
            g_topcov[b * HW + p0 + tid] = 0;
        }
        __syncthreads();

        const int ts  = tid >> 4;        // 8 templates per iteration
        const int ps4 = tid & 15;        // float4 pixel group
        #pragma unroll
        for (int t8 = 0; t8 < TT; t8 += 8) {
            int t = t8 + ts;
            const size_t rb = (size_t)(b * TT + t) * HW + p0;
            float4 tv = __ldcs((const float4*)(temps + rb) + ps4);  // stream
            float4 mv = __ldcs((const float4*)(msks  + rb) + ps4);
            int p = 4 * ps4;
            float d0 = 0.f, d1 = 0.f, d2 = 0.f, d3 = 0.f;
            if (mv.x > MTHR) { float a = sm.pre.xs[p]     - tv.x * mv.x; d0 = a * a - sm.pre.eb[p];     }
            if (mv.y > MTHR) { float a = sm.pre.xs[p + 1] - tv.y * mv.y; d1 = a * a - sm.pre.eb[p + 1]; }
            if (mv.z > MTHR) { float a = sm.pre.xs[p + 2] - tv.z * mv.z; d2 = a * a - sm.pre.eb[p + 2]; }
            if (mv.w > MTHR) { float a = sm.pre.xs[p + 3] - tv.w * mv.w; d3 = a * a - sm.pre.eb[p + 3]; }
            sm.pre.dsm[p][t]     = d0;
            sm.pre.dsm[p + 1][t] = d1;
            sm.pre.dsm[p + 2][t] = d2;
            sm.pre.dsm[p + 3][t] = d3;
        }
        __syncthreads();

        // pack + store D as fp16, t-contiguous: 64*96 halves = 768 uint4
        {
            __half* dst = g_D + ((size_t)b * HW + p0) * TT;
            for (int i = tid; i < 768; i += 128) {
                int r = i / 12, c = (i % 12) * 8;
                __half2 h0 = __floats2half2_rn(sm.pre.dsm[r][c    ], sm.pre.dsm[r][c + 1]);
                __half2 h1 = __floats2half2_rn(sm.pre.dsm[r][c + 2], sm.pre.dsm[r][c + 3]);
                __half2 h2 = __floats2half2_rn(sm.pre.dsm[r][c + 4], sm.pre.dsm[r][c + 5]);
                __half2 h3 = __floats2half2_rn(sm.pre.dsm[r][c + 6], sm.pre.dsm[r][c + 7]);
                uint4 v = make_uint4(*(unsigned*)&h0, *(unsigned*)&h1,
                                     *(unsigned*)&h2, *(unsigned*)&h3);
                *(uint4*)(dst + (size_t)i * 8) = v;
            }
        }

        // delta0 from the SAME half-rounded values (exact incremental invariant)
        if (tid < TT) {
            float s = 0.f;
            #pragma unroll
            for (int p = 0; p < 64; p++)
                s += __half2float(__float2half_rn(sm.pre.dsm[p][tid]));
            accd[tid] += s;
        }
        __syncthreads();   // protect smem reuse next tile
    }
    if (tid < TT)
        atomicAdd(&g_delta[b * TP1 + 1 + tid], (double)accd[tid]);

    grid_barrier(0);

    // ============ Phase B: 6 greedy steps on own 256 pixels ================
    for (int s = 0; s < NSTEP; s++) {
        // --- argmin over 97 candidates (redundant per block, identical) ---
        if (tid < 32) {
            double bestv = 1e300;
            int    besti = TP1;
            for (int t = tid; t < TP1; t += 32) {
                double v = __ldcg(&g_delta[b * TP1 + t]);
                if (used[t]) v = 1e30;
                if (v < bestv) { bestv = v; besti = t; }   // earliest on tie
            }
            for (int off = 16; off; off >>= 1) {
                double ov = __shfl_down_sync(0xffffffffu, bestv, off);
                int    oi = __shfl_down_sync(0xffffffffu, besti, off);
                if (ov < bestv || (ov == bestv && oi < besti)) { bestv = ov; besti = oi; }
            }
            if (tid == 0) {
                sm.st.scid = besti;
                if (besti != 0) used[besti] = 1;
            }
        }
        __syncthreads();
        const int cid = sm.st.scid;

        // --- paint own pixels + deterministic compaction of new ones ---
        int base = 0;
        if (cid != 0) {
            const size_t mrow = (size_t)(b * TT + cid - 1) * HW;
            #pragma unroll
            for (int k = 0; k < PXB / 128; k++) {
                int lp = k * 128 + tid;
                int p  = p0g + lp;
                int q  = b * HW + p;
                bool nw = false;
                float mv = msks[mrow + p];
                if (mv > MTHR && !g_topcov[q]) {
                    g_topval[q] = temps[mrow + p] * mv;  // goes UNDER existing
                    g_topcov[q] = 1;
                    nw = true;
                }
                unsigned m = __ballot_sync(0xffffffffu, nw);
                if ((tid & 31) == 0) sm.st.wm[tid >> 5] = m;
                __syncthreads();
                int off = base, tot = 0;
                #pragma unroll
                for (int w = 0; w < 4; w++) {
                    int c = __popc(sm.st.wm[w]);
                    if (w < (tid >> 5)) off += c;
                    tot += c;
                }
                if (nw) sm.st.list[off + __popc(m & ((1u << (tid & 31)) - 1))] = lp;
                base += tot;
                __syncthreads();
            }
        }
        const int n = base;

        if (s == NSTEP - 1) {
            // --- final composition for own pixels ---
            #pragma unroll
            for (int k = 0; k < PXB / 128; k++) {
                int p = p0g + k * 128 + tid;
                int q = b * HW + p;
                out[q] = g_topcov[q] ? g_topval[q] : bg[p];
            }
        } else {
            // --- gather-subtract fp16 D rows of own new pixels ---
            if (n > 0) {
                if (tid < TT) {
                    const __half* Db = g_D + ((size_t)b * HW + p0g) * TT + tid;
                    float a0 = 0.f, a1 = 0.f, a2 = 0.f, a3 = 0.f;
                    int j = 0;
                    for (; j + 3 < n; j += 4) {
                        a0 += __half2float(Db[(size_t)sm.st.list[j    ] * TT]);
                        a1 += __half2float(Db[(size_t)sm.st.list[j + 1] * TT]);
                        a2 += __half2float(Db[(size_t)sm.st.list[j + 2] * TT]);
                        a3 += __half2float(Db[(size_t)sm.st.list[j + 3] * TT]);
                    }
                    for (; j < n; j++) a0 += __half2float(Db[(size_t)sm.st.list[j] * TT]);
                    float tot = (a0 + a1) + (a2 + a3);
                    atomicAdd(&g_delta[b * TP1 + 1 + tid], -(double)tot);
                }
            }
            grid_barrier(1 + s);
        }
    }
}

// ---------------------------------------------------------------------------
extern "C" void kernel_launch(void* const* d_in, const int* in_sizes, int n_in,
                              void* d_out, int out_size) {
    const float* x      = (const float*)d_in[0];   // (16,1,128,128)
    const float* temps  = (const float*)d_in[1];   // (16,96,1,128,128)
    const float* msks   = (const float*)d_in[2];   // (16,96,1,128,128)
    const float* bg     = (const float*)d_in[3];   // (1,128,128)
    float* out = (float*)d_out;                    // (16,1,128,128)

    k_all<<<NBLK, 128>>>(x, temps, msks, bg, out);
}